// round 8
// baseline (speedup 1.0000x reference)
#include <cuda_runtime.h>
#include <math.h>

// ---------------------------------------------------------------------------
// Problem constants: N=10000, E=160000, D=32, H=16, NB=16, NUM_ATOMS=100,
// CUT=6, DEG=4, OUT=1.
// ---------------------------------------------------------------------------
#define MAXN 10240
#define EMAX 163840

// Scratch (static device globals)
__device__ float4  zg[MAXN * 16];     // per-node {z0, z1x, z1y, z1z} (/DEG folded)
__device__ float2  TABg[100 * 256];   // [a][j*16+h] = {TA, TB}
__device__ float   basisg[EMAX * 16]; // per-edge bessel basis (phase1 -> phase2)
__device__ float4  y1g4[EMAX];        // per-edge l=1 sph harm (w unused)
__device__ double  Gg[512];           // G[h'*16 + j]
__device__ double  S0g[16];           // sum_n z0[n][k]
__device__ unsigned int done_ctr;     // phase2 last-block ticket

// Math constants
#define PI6_D    0.5235987755982988      // pi/6
#define INV2PIF  0.15915494f
#define TWOPI_HI 6.2831855f              // float(2*pi)
#define TWOPI_LO (-1.7484556e-7f)        // 2*pi - (double)TWOPI_HI
#define BSCALEF  2.3094011f              // sqrt(2/6)*sqrt(16)
#define SQ3I4PF  0.48860252f             // sqrt(3)/sqrt(4*pi)
#define Y0C      0.28209479177387814f    // 1/sqrt(4*pi)
#define RSQRT3   0.5773502691896258f     // 1/sqrt(3)
#define C0       0.0031167365657f        // Y0 * (1/sqrt(32)) / 16
#define CBC      0.011048543456039805f   // (1/sqrt(32)) / 16
#define N1D16    0.011048543456039805    // n1/16 (double)

typedef unsigned long long ull;

// f32x2 helpers -------------------------------------------------------------
__device__ __forceinline__ ull pack2(float lo, float hi) {
    float2 f = make_float2(lo, hi);
    ull r; memcpy(&r, &f, 8);
    return r;
}
__device__ __forceinline__ void fma2(ull& acc, ull a, ull b) {
    asm("fma.rn.f32x2 %0, %1, %2, %3;" : "=l"(acc) : "l"(a), "l"(b), "l"(acc));
}
__device__ __forceinline__ ull add2(ull a, ull b) {
    ull r;
    asm("add.rn.f32x2 %0, %1, %2;" : "=l"(r) : "l"(a), "l"(b));
    return r;
}
__device__ __forceinline__ float2 unpack2(ull v) {
    float2 f; memcpy(&f, &v, 8);
    return f;
}

// Fast silu with tight error: __expf ulp<=~6, __fdividef ulp<=2.
__device__ __forceinline__ float fast_silu(float a) {
    float t = __expf(-a);
    return __fdividef(a, 1.0f + t);
}

// sin(n*theta), theta = hi+lo float pair. Residual arg error ~2e-7.
__device__ __forceinline__ float sin_ntheta(float nf, float th_hi, float th_lo) {
    float p = nf * th_hi;
    float perr = fmaf(nf, th_hi, -p);
    float e = fmaf(nf, th_lo, perr);
    float q = rintf(p * INV2PIF);
    float r = fmaf(-q, TWOPI_HI, p);
    r = r + fmaf(-q, TWOPI_LO, e);
    return sinf(r);
}

// ---------------------------------------------------------------------------
// Kernel 0: build TABg + zero zg/Gg/S0g/done_ctr
// ---------------------------------------------------------------------------
__global__ __launch_bounds__(256) void init_kernel(
    const float* __restrict__ atom_emb, const float* __restrict__ fc0_w2,
    int N, int NA)
{
    int b = blockIdx.x;
    int t = threadIdx.x;
    if (b < NA) {
        int j = t >> 4, h = t & 15;
        float ta = 0.0f, tb = 0.0f;
        #pragma unroll
        for (int d = 0; d < 32; d++) {
            float x = atom_emb[b * 32 + d];
            ta += x * fc0_w2[j * 1024 + d * 16 + h];
            tb += x * fc0_w2[j * 1024 + 512 + d * 16 + h];
        }
        TABg[b * 256 + t] = make_float2(ta, tb);
    } else {
        if (b == NA) {
            if (t < 16) S0g[t] = 0.0;
            if (t == 16) done_ctr = 0u;
        }
        if (b == NA + 1) { Gg[t] = 0.0; Gg[t + 256] = 0.0; }
        int tot = N * 16;
        int idx = (b - NA) * 256 + t;
        int stride = (gridDim.x - NA) * 256;
        for (int i = idx; i < tot; i += stride)
            zg[i] = make_float4(0.f, 0.f, 0.f, 0.f);
    }
}

// ---------------------------------------------------------------------------
// Kernel 1: phase-1. Stage 256 edges (thread-per-edge geometry), then
// 16-thread groups consume 16 edges each. Shuffle-based broadcasts, no
// inner syncwarps. One red.v4 atomic per (edge,k). S0 folded in.
// ---------------------------------------------------------------------------
__global__ __launch_bounds__(256) void phase1_kernel(
    const int* __restrict__ an, const float* __restrict__ coords,
    const int* __restrict__ ei, const float* __restrict__ fc0_w1, int E)
{
    __shared__ float sthhi[256], sthlo[256], sbsf[256];
    __shared__ float4 sy1[256];
    __shared__ int sa[256], sdst[256];
    __shared__ float sS0[16];

    int t = threadIdx.x, g = t >> 4, k = t & 15;
    float nf = (float)(k + 1);

    float rw1[16];
    #pragma unroll
    for (int j = 0; j < 16; j++) rw1[j] = fc0_w1[j * 16 + k];

    if (t < 16) sS0[t] = 0.0f;
    float s0acc = 0.0f;

    for (int base = blockIdx.x * 256; base < E; base += gridDim.x * 256) {
        int e = base + t;
        if (e < E) {
            int src = ei[e], dst = ei[E + e];
            float dx = coords[src * 3 + 0] - coords[dst * 3 + 0];
            float dy = coords[src * 3 + 1] - coords[dst * 3 + 1];
            float dz = coords[src * 3 + 2] - coords[dst * 3 + 2];
            double d2 = (double)dx * dx + (double)dy * dy + (double)dz * dz;
            double dist = sqrt(d2);
            float distf = (float)dist;
            float inv = 1.0f / fmaxf(distf, 1e-9f);
            double th = dist * PI6_D;
            float th_hi = (float)th;
            sthhi[t] = th_hi;
            sthlo[t] = (float)(th - (double)th_hi);
            sbsf[t] = (distf < 6.0f) ? (BSCALEF * inv) : 0.0f;
            float4 yv = make_float4(SQ3I4PF * dx * inv, SQ3I4PF * dy * inv,
                                    SQ3I4PF * dz * inv, 0.0f);
            sy1[t] = yv;
            y1g4[e] = yv;
            sa[t] = an[src];
            sdst[t] = dst;
        } else {
            sthhi[t] = 0.0f; sthlo[t] = 0.0f; sbsf[t] = 0.0f;
            sy1[t] = make_float4(0.f, 0.f, 0.f, 0.f);
            sa[t] = 0; sdst[t] = 0;
        }
        __syncthreads();
        int nloc = E - base; if (nloc > 256) nloc = 256;

        #pragma unroll 1
        for (int i = 0; i < 16; i++) {
            int le = g * 16 + i;
            bool eact = le < nloc;
            float bsv = sbsf[le] * sin_ntheta(nf, sthhi[le], sthlo[le]);
            if (eact) basisg[(size_t)(base + le) * 16 + k] = bsv;
            // matvec via half-warp shuffle broadcast (no smem, no syncs)
            float acc = 0.0f;
            #pragma unroll
            for (int j = 0; j < 16; j++)
                acc = fmaf(__shfl_sync(0xffffffffu, bsv, j, 16), rw1[j], acc);
            float h1 = fast_silu(acc * 0.25f);
            int a = sa[le];
            const ull* tab = (const ull*)(TABg + a * 256 + k);
            ull mm = 0ull;
            #pragma unroll
            for (int j = 0; j < 16; j++) {
                float hj = __shfl_sync(0xffffffffu, h1, j, 16);
                fma2(mm, tab[j * 16], pack2(hj, hj));
            }
            if (eact) {
                float2 m = unpack2(mm);
                float m0c = m.x * C0;
                float w = m.y * CBC;
                s0acc += m0c;
                float4 yv = sy1[le];
                float* dp = (float*)&zg[(size_t)sdst[le] * 16 + k];
                asm volatile(
                    "red.global.add.v4.f32 [%0], {%1, %2, %3, %4};"
                    :: "l"(__cvta_generic_to_global(dp)),
                       "f"(m0c), "f"(w * yv.x), "f"(w * yv.y), "f"(w * yv.z)
                    : "memory");
            }
        }
        __syncthreads();
    }

    atomicAdd(&sS0[k], s0acc);
    __syncthreads();
    if (t < 16) atomicAdd(&S0g[t], (double)sS0[t]);
}

// ---------------------------------------------------------------------------
// Kernel 2: phase-2 sum-exchange + fused finale (last-block ticket).
//   G2[m] (lane j=k) = { sum_e h2[e][j]*u0[e][m], sum_e h2[e][j]*u1[e][m] }
//   u0[m]=Y0C*z0, u1[m]=(z1[m]·y1)/sqrt(3). Gg[h'*16+j], h'=m / 16+m.
// ---------------------------------------------------------------------------
__global__ __launch_bounds__(256) void phase2_kernel(
    const int* __restrict__ ei, const float* __restrict__ fc1_w1,
    const float* __restrict__ fc1_w2, const float* __restrict__ w_readout,
    float* __restrict__ out, int E)
{
    __shared__ ull sut2[16][17];
    __shared__ ull swG[8 * 16 * 16];   // 16KB; reused as double scratch in finale
    __shared__ int slast;

    int t = threadIdx.x, g = t >> 4, k = t & 15;

    float rw1[16];
    #pragma unroll
    for (int j = 0; j < 16; j++) rw1[j] = fc1_w1[j * 16 + k];

    ull G2[16];
    #pragma unroll
    for (int m = 0; m < 16; m++) G2[m] = 0ull;

    for (int base = blockIdx.x * 256; base < E; base += gridDim.x * 256) {
        int nloc = E - base; if (nloc > 256) nloc = 256;
        #pragma unroll 1
        for (int i = 0; i < 16; i++) {
            int le = g * 16 + i;
            bool eact = le < nloc;
            int e0 = eact ? (base + le) : base;
            float b = basisg[(size_t)e0 * 16 + k];
            float acc = 0.0f;
            #pragma unroll
            for (int j = 0; j < 16; j++)
                acc = fmaf(__shfl_sync(0xffffffffu, b, j, 16), rw1[j], acc);
            float h2 = fast_silu(acc * 0.25f);
            if (!eact) h2 = 0.0f;
            int src = ei[e0];
            float4 yv = y1g4[e0];
            float4 zv = zg[(size_t)src * 16 + k];
            float u0 = Y0C * zv.x;
            float u1 = (zv.y * yv.x + zv.z * yv.y + zv.w * yv.z) * RSQRT3;
            sut2[g][k] = pack2(u0, u1);
            __syncwarp();
            ull h22 = pack2(h2, h2);
            #pragma unroll
            for (int m = 0; m < 16; m++) fma2(G2[m], sut2[g][m], h22);
            __syncwarp();
        }
    }

    // reduce the two half-warp groups within each warp
    #pragma unroll
    for (int m = 0; m < 16; m++)
        G2[m] = add2(G2[m], __shfl_down_sync(0xffffffffu, G2[m], 16));
    int w = t >> 5;
    if ((t & 16) == 0) {
        #pragma unroll
        for (int m = 0; m < 16; m++) swG[(w * 16 + k) * 16 + m] = G2[m];
    }
    __syncthreads();
    {
        int k2 = t & 15, m = t >> 4;
        double glo = 0.0, ghi = 0.0;
        #pragma unroll
        for (int w2 = 0; w2 < 8; w2++) {
            float2 f = unpack2(swG[(w2 * 16 + k2) * 16 + m]);
            glo += (double)f.x;
            ghi += (double)f.y;
        }
        atomicAdd(&Gg[m * 16 + k2], glo);
        atomicAdd(&Gg[(16 + m) * 16 + k2], ghi);
    }

    // ---- last-block ticket ----
    __threadfence();
    __syncthreads();
    if (t == 0) {
        unsigned int tk = atomicAdd(&done_ctr, 1u);
        slast = (tk == gridDim.x - 1) ? 1 : 0;
    }
    __syncthreads();
    if (!slast) return;
    __threadfence();

    // ---- finale (non-spilling, 2 ILP accumulators) ----
    volatile double* vG = Gg;
    volatile double* vS0 = S0g;
    int kk = t & 15, j = t >> 4;
    const float* wrow = fc1_w2 + j * 1024;
    double oc0 = 0.0, oc1 = 0.0;
    #pragma unroll
    for (int hp = 0; hp < 16; hp += 2) {
        oc0 += vG[hp * 16 + j]        * (double)wrow[hp * 16 + kk];
        oc1 += vG[(hp + 1) * 16 + j]  * (double)wrow[(hp + 1) * 16 + kk];
        oc0 += vG[(16 + hp) * 16 + j] * (double)wrow[768 + hp * 16 + kk];
        oc1 += vG[(17 + hp) * 16 + j] * (double)wrow[768 + (hp + 1) * 16 + kk];
    }
    __syncthreads();   // all raw swG reads above are done; safe to repurpose
    double* sred = (double*)swG;   // 256 doubles
    double* sterm = sred + 256;    // 16 doubles
    sred[t] = oc0 + oc1;
    __syncthreads();
    if (t < 16) {
        double s = 0.0;
        for (int j2 = 0; j2 < 16; j2++) s += sred[j2 * 16 + t];
        sterm[t] = (s * N1D16 + vS0[t]) * (double)w_readout[t] * 0.25;
    }
    __syncthreads();
    if (t == 0) {
        double s = 0.0;
        for (int i = 0; i < 16; i++) s += sterm[i];
        out[0] = (float)s;
    }
}

// ---------------------------------------------------------------------------
// Launch
// ---------------------------------------------------------------------------
extern "C" void kernel_launch(void* const* d_in, const int* in_sizes, int n_in,
                              void* d_out, int out_size)
{
    const int*   an        = (const int*)  d_in[0];
    const float* coords    = (const float*)d_in[1];
    const int*   ei        = (const int*)  d_in[2];
    const float* atom_emb  = (const float*)d_in[3];
    const float* fc0_w1    = (const float*)d_in[4];
    const float* fc0_w2    = (const float*)d_in[5];
    const float* fc1_w1    = (const float*)d_in[6];
    const float* fc1_w2    = (const float*)d_in[7];
    const float* w_readout = (const float*)d_in[8];
    float* out = (float*)d_out;

    int N  = in_sizes[0];
    int E  = in_sizes[2] / 2;
    int NA = in_sizes[3] / 32;   // 100 atom types

    int gp = (E + 255) / 256;    // 625 blocks: one sweep

    init_kernel<<<NA + 512, 256>>>(atom_emb, fc0_w2, N, NA);
    phase1_kernel<<<gp, 256>>>(an, coords, ei, fc0_w1, E);
    phase2_kernel<<<gp, 256>>>(ei, fc1_w1, fc1_w2, w_readout, out, E);
}

// round 9
// speedup vs baseline: 1.0788x; 1.0788x over previous
#include <cuda_runtime.h>
#include <math.h>

// ---------------------------------------------------------------------------
// Problem constants: N=10000, E=160000, D=32, H=16, NB=16, NUM_ATOMS=100,
// CUT=6, DEG=4, OUT=1.
// ---------------------------------------------------------------------------
#define MAXN 10240
#define EMAX 163840

// Scratch (static device globals)
__device__ float4  zg[MAXN * 16];     // per-node {z0, z1x, z1y, z1z} (/DEG folded)
__device__ float2  TABg[100 * 256];   // [a][j*16+h] = {TA, TB}
__device__ float   h2g[EMAX * 16];    // per-edge phase-2 hidden vec (phase1 -> phase2)
__device__ float4  y1g4[EMAX];        // per-edge l=1 sph harm (w unused)
__device__ double  Gg[512];           // G[h'*16 + j]
__device__ double  S0g[16];           // sum_n z0[n][k]
__device__ unsigned int done_ctr;     // phase2 last-block ticket

// Math constants
#define PI6_D    0.5235987755982988      // pi/6
#define INV2PIF  0.15915494f
#define TWOPI_HI 6.2831855f              // float(2*pi)
#define TWOPI_LO (-1.7484556e-7f)        // 2*pi - (double)TWOPI_HI
#define BSCALEF  2.3094011f              // sqrt(2/6)*sqrt(16)
#define SQ3I4PF  0.48860252f             // sqrt(3)/sqrt(4*pi)
#define Y0C      0.28209479177387814f    // 1/sqrt(4*pi)
#define RSQRT3   0.5773502691896258f     // 1/sqrt(3)
#define C0       0.0031167365657f        // Y0 * (1/sqrt(32)) / 16
#define CBC      0.011048543456039805f   // (1/sqrt(32)) / 16
#define N1D16    0.011048543456039805    // n1/16 (double)

typedef unsigned long long ull;

// f32x2 helpers -------------------------------------------------------------
__device__ __forceinline__ ull pack2(float lo, float hi) {
    float2 f = make_float2(lo, hi);
    ull r; memcpy(&r, &f, 8);
    return r;
}
__device__ __forceinline__ void fma2(ull& acc, ull a, ull b) {
    asm("fma.rn.f32x2 %0, %1, %2, %3;" : "=l"(acc) : "l"(a), "l"(b), "l"(acc));
}
__device__ __forceinline__ ull add2(ull a, ull b) {
    ull r;
    asm("add.rn.f32x2 %0, %1, %2;" : "=l"(r) : "l"(a), "l"(b));
    return r;
}
__device__ __forceinline__ float2 unpack2(ull v) {
    float2 f; memcpy(&f, &v, 8);
    return f;
}

// Fast silu with tight error: __expf ulp<=~6, __fdividef ulp<=2.
__device__ __forceinline__ float fast_silu(float a) {
    float t = __expf(-a);
    return __fdividef(a, 1.0f + t);
}

// sin(n*theta), theta = hi+lo float pair. Residual arg error ~2e-7.
__device__ __forceinline__ float sin_ntheta(float nf, float th_hi, float th_lo) {
    float p = nf * th_hi;
    float perr = fmaf(nf, th_hi, -p);
    float e = fmaf(nf, th_lo, perr);
    float q = rintf(p * INV2PIF);
    float r = fmaf(-q, TWOPI_HI, p);
    r = r + fmaf(-q, TWOPI_LO, e);
    return sinf(r);
}

// ---------------------------------------------------------------------------
// Kernel 0: build TABg + zero zg/Gg/S0g/done_ctr
// ---------------------------------------------------------------------------
__global__ __launch_bounds__(256) void init_kernel(
    const float* __restrict__ atom_emb, const float* __restrict__ fc0_w2,
    int N, int NA)
{
    int b = blockIdx.x;
    int t = threadIdx.x;
    if (b < NA) {
        int j = t >> 4, h = t & 15;
        float ta = 0.0f, tb = 0.0f;
        #pragma unroll
        for (int d = 0; d < 32; d++) {
            float x = atom_emb[b * 32 + d];
            ta += x * fc0_w2[j * 1024 + d * 16 + h];
            tb += x * fc0_w2[j * 1024 + 512 + d * 16 + h];
        }
        TABg[b * 256 + t] = make_float2(ta, tb);
    } else {
        if (b == NA) {
            if (t < 16) S0g[t] = 0.0;
            if (t == 16) done_ctr = 0u;
        }
        if (b == NA + 1) { Gg[t] = 0.0; Gg[t + 256] = 0.0; }
        int tot = N * 16;
        int idx = (b - NA) * 256 + t;
        int stride = (gridDim.x - NA) * 256;
        for (int i = idx; i < tot; i += stride)
            zg[i] = make_float4(0.f, 0.f, 0.f, 0.f);
    }
}

// ---------------------------------------------------------------------------
// Kernel 1: phase-1. Stage 256 edges (thread-per-edge geometry), then
// 16-thread groups consume 16 edges each (unroll 2, independent chains).
// Dual matvec (f32x2): one 16-FFMA2 chain produces both h1 AND h2.
// h2 cached to h2g for phase2. One red.v4 atomic per (edge,k). S0 folded.
// ---------------------------------------------------------------------------
__global__ __launch_bounds__(256) void phase1_kernel(
    const int* __restrict__ an, const float* __restrict__ coords,
    const int* __restrict__ ei, const float* __restrict__ fc0_w1,
    const float* __restrict__ fc1_w1, int E)
{
    __shared__ float sthhi[256], sthlo[256], sbsf[256];
    __shared__ float4 sy1[256];
    __shared__ int sa[256], sdst[256];
    __shared__ float sS0[16];

    int t = threadIdx.x, g = t >> 4, k = t & 15;
    float nf = (float)(k + 1);

    // packed weight columns: {fc0_w1[j][k], fc1_w1[j][k]}
    ull rw12[16];
    #pragma unroll
    for (int j = 0; j < 16; j++)
        rw12[j] = pack2(fc0_w1[j * 16 + k], fc1_w1[j * 16 + k]);

    if (t < 16) sS0[t] = 0.0f;
    float s0acc = 0.0f;

    for (int base = blockIdx.x * 256; base < E; base += gridDim.x * 256) {
        int e = base + t;
        if (e < E) {
            int src = ei[e], dst = ei[E + e];
            float dx = coords[src * 3 + 0] - coords[dst * 3 + 0];
            float dy = coords[src * 3 + 1] - coords[dst * 3 + 1];
            float dz = coords[src * 3 + 2] - coords[dst * 3 + 2];
            double d2 = (double)dx * dx + (double)dy * dy + (double)dz * dz;
            double dist = sqrt(d2);
            float distf = (float)dist;
            float inv = 1.0f / fmaxf(distf, 1e-9f);
            double th = dist * PI6_D;
            float th_hi = (float)th;
            sthhi[t] = th_hi;
            sthlo[t] = (float)(th - (double)th_hi);
            sbsf[t] = (distf < 6.0f) ? (BSCALEF * inv) : 0.0f;
            float4 yv = make_float4(SQ3I4PF * dx * inv, SQ3I4PF * dy * inv,
                                    SQ3I4PF * dz * inv, 0.0f);
            sy1[t] = yv;
            y1g4[e] = yv;
            sa[t] = an[src];
            sdst[t] = dst;
        } else {
            sthhi[t] = 0.0f; sthlo[t] = 0.0f; sbsf[t] = 0.0f;
            sy1[t] = make_float4(0.f, 0.f, 0.f, 0.f);
            sa[t] = 0; sdst[t] = 0;
        }
        __syncthreads();
        int nloc = E - base; if (nloc > 256) nloc = 256;

        #pragma unroll 2
        for (int i = 0; i < 16; i++) {
            int le = g * 16 + i;
            bool eact = le < nloc;
            float bsv = sbsf[le] * sin_ntheta(nf, sthhi[le], sthlo[le]);
            // dual matvec: {h1-acc, h2-acc} via packed FMA on shfl broadcast
            ull acc2 = 0ull;
            #pragma unroll
            for (int j = 0; j < 16; j++) {
                float bj = __shfl_sync(0xffffffffu, bsv, j, 16);
                fma2(acc2, pack2(bj, bj), rw12[j]);
            }
            float2 ac = unpack2(acc2);
            float h1 = fast_silu(ac.x * 0.25f);
            float h2 = fast_silu(ac.y * 0.25f);
            if (eact) h2g[(size_t)(base + le) * 16 + k] = h2;
            int a = sa[le];
            const ull* tab = (const ull*)(TABg + a * 256 + k);
            ull mm = 0ull;
            #pragma unroll
            for (int j = 0; j < 16; j++) {
                float hj = __shfl_sync(0xffffffffu, h1, j, 16);
                fma2(mm, tab[j * 16], pack2(hj, hj));
            }
            if (eact) {
                float2 m = unpack2(mm);
                float m0c = m.x * C0;
                float w = m.y * CBC;
                s0acc += m0c;
                float4 yv = sy1[le];
                float* dp = (float*)&zg[(size_t)sdst[le] * 16 + k];
                asm volatile(
                    "red.global.add.v4.f32 [%0], {%1, %2, %3, %4};"
                    :: "l"(__cvta_generic_to_global(dp)),
                       "f"(m0c), "f"(w * yv.x), "f"(w * yv.y), "f"(w * yv.z)
                    : "memory");
            }
        }
        __syncthreads();
    }

    atomicAdd(&sS0[k], s0acc);
    __syncthreads();
    if (t < 16) atomicAdd(&S0g[t], (double)sS0[t]);
}

// ---------------------------------------------------------------------------
// Kernel 2: phase-2 sum-exchange + fused finale (last-block ticket).
// Slim inner loop: LDG h2 / y1 / zg, STS u-pair (double-buffered), 16 FFMA2.
//   G2[m] (lane j=k) = { sum_e h2[e][j]*u0[e][m], sum_e h2[e][j]*u1[e][m] }
//   u0[m]=Y0C*z0, u1[m]=(z1[m]·y1)/sqrt(3). Gg[h'*16+j], h'=m / 16+m.
// ---------------------------------------------------------------------------
__global__ __launch_bounds__(256) void phase2_kernel(
    const int* __restrict__ ei,
    const float* __restrict__ fc1_w2, const float* __restrict__ w_readout,
    float* __restrict__ out, int E)
{
    __shared__ ull sut2[2][16][17];    // double-buffered u-pair staging
    __shared__ ull swG[8 * 16 * 16];   // 16KB; reused as double scratch in finale
    __shared__ int slast;

    int t = threadIdx.x, g = t >> 4, k = t & 15;

    ull G2[16];
    #pragma unroll
    for (int m = 0; m < 16; m++) G2[m] = 0ull;

    for (int base = blockIdx.x * 256; base < E; base += gridDim.x * 256) {
        int nloc = E - base; if (nloc > 256) nloc = 256;
        #pragma unroll 2
        for (int i = 0; i < 16; i++) {
            int p = i & 1;
            int le = g * 16 + i;
            bool eact = le < nloc;
            int e0 = eact ? (base + le) : base;
            float h2 = h2g[(size_t)e0 * 16 + k];
            if (!eact) h2 = 0.0f;
            int src = ei[e0];
            float4 yv = y1g4[e0];
            float4 zv = zg[(size_t)src * 16 + k];
            float u0 = Y0C * zv.x;
            float u1 = (zv.y * yv.x + zv.z * yv.y + zv.w * yv.z) * RSQRT3;
            sut2[p][g][k] = pack2(u0, u1);
            __syncwarp();
            ull h22 = pack2(h2, h2);
            #pragma unroll
            for (int m = 0; m < 16; m++) fma2(G2[m], sut2[p][g][m], h22);
        }
    }

    // reduce the two half-warp groups within each warp
    #pragma unroll
    for (int m = 0; m < 16; m++)
        G2[m] = add2(G2[m], __shfl_down_sync(0xffffffffu, G2[m], 16));
    int w = t >> 5;
    if ((t & 16) == 0) {
        #pragma unroll
        for (int m = 0; m < 16; m++) swG[(w * 16 + k) * 16 + m] = G2[m];
    }
    __syncthreads();
    {
        int k2 = t & 15, m = t >> 4;
        double glo = 0.0, ghi = 0.0;
        #pragma unroll
        for (int w2 = 0; w2 < 8; w2++) {
            float2 f = unpack2(swG[(w2 * 16 + k2) * 16 + m]);
            glo += (double)f.x;
            ghi += (double)f.y;
        }
        atomicAdd(&Gg[m * 16 + k2], glo);
        atomicAdd(&Gg[(16 + m) * 16 + k2], ghi);
    }

    // ---- last-block ticket ----
    __threadfence();
    __syncthreads();
    if (t == 0) {
        unsigned int tk = atomicAdd(&done_ctr, 1u);
        slast = (tk == gridDim.x - 1) ? 1 : 0;
    }
    __syncthreads();
    if (!slast) return;
    __threadfence();

    // ---- finale (non-spilling, 2 ILP accumulators) ----
    volatile double* vG = Gg;
    volatile double* vS0 = S0g;
    int kk = t & 15, j = t >> 4;
    const float* wrow = fc1_w2 + j * 1024;
    double oc0 = 0.0, oc1 = 0.0;
    #pragma unroll
    for (int hp = 0; hp < 16; hp += 2) {
        oc0 += vG[hp * 16 + j]        * (double)wrow[hp * 16 + kk];
        oc1 += vG[(hp + 1) * 16 + j]  * (double)wrow[(hp + 1) * 16 + kk];
        oc0 += vG[(16 + hp) * 16 + j] * (double)wrow[768 + hp * 16 + kk];
        oc1 += vG[(17 + hp) * 16 + j] * (double)wrow[768 + (hp + 1) * 16 + kk];
    }
    __syncthreads();   // all raw swG reads above are done; safe to repurpose
    double* sred = (double*)swG;   // 256 doubles
    double* sterm = sred + 256;    // 16 doubles
    sred[t] = oc0 + oc1;
    __syncthreads();
    if (t < 16) {
        double s = 0.0;
        for (int j2 = 0; j2 < 16; j2++) s += sred[j2 * 16 + t];
        sterm[t] = (s * N1D16 + vS0[t]) * (double)w_readout[t] * 0.25;
    }
    __syncthreads();
    if (t == 0) {
        double s = 0.0;
        for (int i = 0; i < 16; i++) s += sterm[i];
        out[0] = (float)s;
    }
}

// ---------------------------------------------------------------------------
// Launch
// ---------------------------------------------------------------------------
extern "C" void kernel_launch(void* const* d_in, const int* in_sizes, int n_in,
                              void* d_out, int out_size)
{
    const int*   an        = (const int*)  d_in[0];
    const float* coords    = (const float*)d_in[1];
    const int*   ei        = (const int*)  d_in[2];
    const float* atom_emb  = (const float*)d_in[3];
    const float* fc0_w1    = (const float*)d_in[4];
    const float* fc0_w2    = (const float*)d_in[5];
    const float* fc1_w1    = (const float*)d_in[6];
    const float* fc1_w2    = (const float*)d_in[7];
    const float* w_readout = (const float*)d_in[8];
    float* out = (float*)d_out;

    int N  = in_sizes[0];
    int E  = in_sizes[2] / 2;
    int NA = in_sizes[3] / 32;   // 100 atom types

    int gp = (E + 255) / 256;    // 625 blocks: one sweep

    init_kernel<<<NA + 512, 256>>>(atom_emb, fc0_w2, N, NA);
    phase1_kernel<<<gp, 256>>>(an, coords, ei, fc0_w1, fc1_w1, E);
    phase2_kernel<<<gp, 256>>>(ei, fc1_w2, w_readout, out, E);
}

// round 10
// speedup vs baseline: 1.1075x; 1.0266x over previous
#include <cuda_runtime.h>
#include <math.h>

// ---------------------------------------------------------------------------
// Problem constants: N=10000, E=160000, D=32, H=16, NB=16, NUM_ATOMS=100,
// CUT=6, DEG=4, OUT=1.
// ---------------------------------------------------------------------------
#define MAXN 10240
#define EMAX 163840
#define GP   592          // 148 SMs x 4 blocks: one resident wave

// Scratch (static device globals)
__device__ float4  zg[MAXN * 16];     // per-node {z0, z1x, z1y, z1z} (/DEG folded)
__device__ float2  TABg[100 * 256];   // [a][j*16+h] = {TA, TB}
__device__ float   h2g[EMAX * 16];    // per-edge phase-2 hidden vec (phase1 -> phase2)
__device__ float4  y1g4[EMAX];        // per-edge l=1 sph harm (w unused)
__device__ double  Gg[512];           // G[h'*16 + j]
__device__ double  S0g[16];           // sum_n z0[n][k]
__device__ unsigned int done_ctr;     // phase2 last-block ticket
__device__ unsigned int p1_ctr;       // phase1 batch ticket
__device__ unsigned int p2_ctr;       // phase2 batch ticket

// Math constants
#define PI6_D    0.5235987755982988      // pi/6
#define INV2PIF  0.15915494f
#define TWOPI_HI 6.2831855f              // float(2*pi)
#define TWOPI_LO (-1.7484556e-7f)        // 2*pi - (double)TWOPI_HI
#define BSCALEF  2.3094011f              // sqrt(2/6)*sqrt(16)
#define SQ3I4PF  0.48860252f             // sqrt(3)/sqrt(4*pi)
#define Y0C      0.28209479177387814f    // 1/sqrt(4*pi)
#define RSQRT3   0.5773502691896258f     // 1/sqrt(3)
#define C0       0.0031167365657f        // Y0 * (1/sqrt(32)) / 16
#define CBC      0.011048543456039805f   // (1/sqrt(32)) / 16
#define N1D16    0.011048543456039805    // n1/16 (double)

typedef unsigned long long ull;

// f32x2 helpers -------------------------------------------------------------
__device__ __forceinline__ ull pack2(float lo, float hi) {
    float2 f = make_float2(lo, hi);
    ull r; memcpy(&r, &f, 8);
    return r;
}
__device__ __forceinline__ void fma2(ull& acc, ull a, ull b) {
    asm("fma.rn.f32x2 %0, %1, %2, %3;" : "=l"(acc) : "l"(a), "l"(b), "l"(acc));
}
__device__ __forceinline__ ull add2(ull a, ull b) {
    ull r;
    asm("add.rn.f32x2 %0, %1, %2;" : "=l"(r) : "l"(a), "l"(b));
    return r;
}
__device__ __forceinline__ float2 unpack2(ull v) {
    float2 f; memcpy(&f, &v, 8);
    return f;
}

// Fast silu with tight error: __expf ulp<=~6, __fdividef ulp<=2.
__device__ __forceinline__ float fast_silu(float a) {
    float t = __expf(-a);
    return __fdividef(a, 1.0f + t);
}

// sin(n*theta), theta = hi+lo float pair. Residual arg error ~2e-7.
__device__ __forceinline__ float sin_ntheta(float nf, float th_hi, float th_lo) {
    float p = nf * th_hi;
    float perr = fmaf(nf, th_hi, -p);
    float e = fmaf(nf, th_lo, perr);
    float q = rintf(p * INV2PIF);
    float r = fmaf(-q, TWOPI_HI, p);
    r = r + fmaf(-q, TWOPI_LO, e);
    return sinf(r);
}

// ---------------------------------------------------------------------------
// Kernel 0: build TABg + zero zg/Gg/S0g/tickets
// ---------------------------------------------------------------------------
__global__ __launch_bounds__(256) void init_kernel(
    const float* __restrict__ atom_emb, const float* __restrict__ fc0_w2,
    int N, int NA)
{
    int b = blockIdx.x;
    int t = threadIdx.x;
    if (b < NA) {
        int j = t >> 4, h = t & 15;
        float ta = 0.0f, tb = 0.0f;
        #pragma unroll
        for (int d = 0; d < 32; d++) {
            float x = atom_emb[b * 32 + d];
            ta += x * fc0_w2[j * 1024 + d * 16 + h];
            tb += x * fc0_w2[j * 1024 + 512 + d * 16 + h];
        }
        TABg[b * 256 + t] = make_float2(ta, tb);
    } else {
        if (b == NA) {
            if (t < 16) S0g[t] = 0.0;
            if (t == 16) done_ctr = 0u;
            if (t == 17) p1_ctr = 0u;
            if (t == 18) p2_ctr = 0u;
        }
        if (b == NA + 1) { Gg[t] = 0.0; Gg[t + 256] = 0.0; }
        int tot = N * 16;
        int idx = (b - NA) * 256 + t;
        int stride = (gridDim.x - NA) * 256;
        for (int i = idx; i < tot; i += stride)
            zg[i] = make_float4(0.f, 0.f, 0.f, 0.f);
    }
}

// ---------------------------------------------------------------------------
// Kernel 1: phase-1 with work-stealing batches. Stage 256 edges
// (thread-per-edge geometry), then 16-thread groups consume 16 edges each
// (unroll 2). Dual matvec (f32x2) yields h1 AND h2; h2 cached for phase2.
// One red.v4 atomic per (edge,k). S0 folded in.
// ---------------------------------------------------------------------------
__global__ __launch_bounds__(256) void phase1_kernel(
    const int* __restrict__ an, const float* __restrict__ coords,
    const int* __restrict__ ei, const float* __restrict__ fc0_w1,
    const float* __restrict__ fc1_w1, int E)
{
    __shared__ float sthhi[256], sthlo[256], sbsf[256];
    __shared__ float4 sy1[256];
    __shared__ int sa[256], sdst[256];
    __shared__ float sS0[16];
    __shared__ int sbase;

    int t = threadIdx.x, g = t >> 4, k = t & 15;
    float nf = (float)(k + 1);

    // packed weight columns: {fc0_w1[j][k], fc1_w1[j][k]}
    ull rw12[16];
    #pragma unroll
    for (int j = 0; j < 16; j++)
        rw12[j] = pack2(fc0_w1[j * 16 + k], fc1_w1[j * 16 + k]);

    if (t < 16) sS0[t] = 0.0f;
    float s0acc = 0.0f;

    for (;;) {
        if (t == 0) sbase = (int)(atomicAdd(&p1_ctr, 1u) * 256u);
        __syncthreads();
        int base = sbase;
        if (base >= E) break;

        int e = base + t;
        if (e < E) {
            int src = ei[e], dst = ei[E + e];
            float dx = coords[src * 3 + 0] - coords[dst * 3 + 0];
            float dy = coords[src * 3 + 1] - coords[dst * 3 + 1];
            float dz = coords[src * 3 + 2] - coords[dst * 3 + 2];
            double d2 = (double)dx * dx + (double)dy * dy + (double)dz * dz;
            double dist = sqrt(d2);
            float distf = (float)dist;
            float inv = 1.0f / fmaxf(distf, 1e-9f);
            double th = dist * PI6_D;
            float th_hi = (float)th;
            sthhi[t] = th_hi;
            sthlo[t] = (float)(th - (double)th_hi);
            sbsf[t] = (distf < 6.0f) ? (BSCALEF * inv) : 0.0f;
            float4 yv = make_float4(SQ3I4PF * dx * inv, SQ3I4PF * dy * inv,
                                    SQ3I4PF * dz * inv, 0.0f);
            sy1[t] = yv;
            y1g4[e] = yv;
            sa[t] = an[src];
            sdst[t] = dst;
        } else {
            sthhi[t] = 0.0f; sthlo[t] = 0.0f; sbsf[t] = 0.0f;
            sy1[t] = make_float4(0.f, 0.f, 0.f, 0.f);
            sa[t] = 0; sdst[t] = 0;
        }
        __syncthreads();
        int nloc = E - base; if (nloc > 256) nloc = 256;

        #pragma unroll 2
        for (int i = 0; i < 16; i++) {
            int le = g * 16 + i;
            bool eact = le < nloc;
            float bsv = sbsf[le] * sin_ntheta(nf, sthhi[le], sthlo[le]);
            // dual matvec: {h1-acc, h2-acc} via packed FMA on shfl broadcast
            ull acc2 = 0ull;
            #pragma unroll
            for (int j = 0; j < 16; j++) {
                float bj = __shfl_sync(0xffffffffu, bsv, j, 16);
                fma2(acc2, pack2(bj, bj), rw12[j]);
            }
            float2 ac = unpack2(acc2);
            float h1 = fast_silu(ac.x * 0.25f);
            float h2 = fast_silu(ac.y * 0.25f);
            if (eact) h2g[(size_t)(base + le) * 16 + k] = h2;
            int a = sa[le];
            const ull* tab = (const ull*)(TABg + a * 256 + k);
            ull mm = 0ull;
            #pragma unroll
            for (int j = 0; j < 16; j++) {
                float hj = __shfl_sync(0xffffffffu, h1, j, 16);
                fma2(mm, tab[j * 16], pack2(hj, hj));
            }
            if (eact) {
                float2 m = unpack2(mm);
                float m0c = m.x * C0;
                float w = m.y * CBC;
                s0acc += m0c;
                float4 yv = sy1[le];
                float* dp = (float*)&zg[(size_t)sdst[le] * 16 + k];
                asm volatile(
                    "red.global.add.v4.f32 [%0], {%1, %2, %3, %4};"
                    :: "l"(__cvta_generic_to_global(dp)),
                       "f"(m0c), "f"(w * yv.x), "f"(w * yv.y), "f"(w * yv.z)
                    : "memory");
            }
        }
        __syncthreads();
    }

    atomicAdd(&sS0[k], s0acc);
    __syncthreads();
    if (t < 16) atomicAdd(&S0g[t], (double)sS0[t]);
}

// ---------------------------------------------------------------------------
// Kernel 2: phase-2 sum-exchange with work-stealing + fused finale.
// Slim inner loop: LDG h2 / y1 / zg, STS u-pair (double-buffered), 16 FFMA2.
//   G2[m] (lane j=k) = { sum_e h2[e][j]*u0[e][m], sum_e h2[e][j]*u1[e][m] }
//   u0[m]=Y0C*z0, u1[m]=(z1[m]·y1)/sqrt(3). Gg[h'*16+j], h'=m / 16+m.
// ---------------------------------------------------------------------------
__global__ __launch_bounds__(256) void phase2_kernel(
    const int* __restrict__ ei,
    const float* __restrict__ fc1_w2, const float* __restrict__ w_readout,
    float* __restrict__ out, int E)
{
    __shared__ ull sut2[2][16][17];    // double-buffered u-pair staging
    __shared__ ull swG[8 * 16 * 16];   // 16KB; reused as double scratch in finale
    __shared__ int slast;
    __shared__ int sbase;

    int t = threadIdx.x, g = t >> 4, k = t & 15;

    ull G2[16];
    #pragma unroll
    for (int m = 0; m < 16; m++) G2[m] = 0ull;

    for (;;) {
        if (t == 0) sbase = (int)(atomicAdd(&p2_ctr, 1u) * 256u);
        __syncthreads();
        int base = sbase;
        if (base >= E) break;
        int nloc = E - base; if (nloc > 256) nloc = 256;

        #pragma unroll 2
        for (int i = 0; i < 16; i++) {
            int p = i & 1;
            int le = g * 16 + i;
            bool eact = le < nloc;
            int e0 = eact ? (base + le) : base;
            float h2 = h2g[(size_t)e0 * 16 + k];
            if (!eact) h2 = 0.0f;
            int src = ei[e0];
            float4 yv = y1g4[e0];
            float4 zv = zg[(size_t)src * 16 + k];
            float u0 = Y0C * zv.x;
            float u1 = (zv.y * yv.x + zv.z * yv.y + zv.w * yv.z) * RSQRT3;
            sut2[p][g][k] = pack2(u0, u1);
            __syncwarp();
            ull h22 = pack2(h2, h2);
            #pragma unroll
            for (int m = 0; m < 16; m++) fma2(G2[m], sut2[p][g][m], h22);
        }
        __syncthreads();
    }

    // reduce the two half-warp groups within each warp
    #pragma unroll
    for (int m = 0; m < 16; m++)
        G2[m] = add2(G2[m], __shfl_down_sync(0xffffffffu, G2[m], 16));
    int w = t >> 5;
    if ((t & 16) == 0) {
        #pragma unroll
        for (int m = 0; m < 16; m++) swG[(w * 16 + k) * 16 + m] = G2[m];
    }
    __syncthreads();
    {
        int k2 = t & 15, m = t >> 4;
        double glo = 0.0, ghi = 0.0;
        #pragma unroll
        for (int w2 = 0; w2 < 8; w2++) {
            float2 f = unpack2(swG[(w2 * 16 + k2) * 16 + m]);
            glo += (double)f.x;
            ghi += (double)f.y;
        }
        atomicAdd(&Gg[m * 16 + k2], glo);
        atomicAdd(&Gg[(16 + m) * 16 + k2], ghi);
    }

    // ---- last-block ticket ----
    __threadfence();
    __syncthreads();
    if (t == 0) {
        unsigned int tk = atomicAdd(&done_ctr, 1u);
        slast = (tk == gridDim.x - 1) ? 1 : 0;
    }
    __syncthreads();
    if (!slast) return;
    __threadfence();

    // ---- finale (non-spilling, 2 ILP accumulators) ----
    volatile double* vG = Gg;
    volatile double* vS0 = S0g;
    int kk = t & 15, j = t >> 4;
    const float* wrow = fc1_w2 + j * 1024;
    double oc0 = 0.0, oc1 = 0.0;
    #pragma unroll
    for (int hp = 0; hp < 16; hp += 2) {
        oc0 += vG[hp * 16 + j]        * (double)wrow[hp * 16 + kk];
        oc1 += vG[(hp + 1) * 16 + j]  * (double)wrow[(hp + 1) * 16 + kk];
        oc0 += vG[(16 + hp) * 16 + j] * (double)wrow[768 + hp * 16 + kk];
        oc1 += vG[(17 + hp) * 16 + j] * (double)wrow[768 + (hp + 1) * 16 + kk];
    }
    __syncthreads();   // all raw swG reads above are done; safe to repurpose
    double* sred = (double*)swG;   // 256 doubles
    double* sterm = sred + 256;    // 16 doubles
    sred[t] = oc0 + oc1;
    __syncthreads();
    if (t < 16) {
        double s = 0.0;
        for (int j2 = 0; j2 < 16; j2++) s += sred[j2 * 16 + t];
        sterm[t] = (s * N1D16 + vS0[t]) * (double)w_readout[t] * 0.25;
    }
    __syncthreads();
    if (t == 0) {
        double s = 0.0;
        for (int i = 0; i < 16; i++) s += sterm[i];
        out[0] = (float)s;
    }
}

// ---------------------------------------------------------------------------
// Launch
// ---------------------------------------------------------------------------
extern "C" void kernel_launch(void* const* d_in, const int* in_sizes, int n_in,
                              void* d_out, int out_size)
{
    const int*   an        = (const int*)  d_in[0];
    const float* coords    = (const float*)d_in[1];
    const int*   ei        = (const int*)  d_in[2];
    const float* atom_emb  = (const float*)d_in[3];
    const float* fc0_w1    = (const float*)d_in[4];
    const float* fc0_w2    = (const float*)d_in[5];
    const float* fc1_w1    = (const float*)d_in[6];
    const float* fc1_w2    = (const float*)d_in[7];
    const float* w_readout = (const float*)d_in[8];
    float* out = (float*)d_out;

    int N  = in_sizes[0];
    int E  = in_sizes[2] / 2;
    int NA = in_sizes[3] / 32;   // 100 atom types

    init_kernel<<<NA + 512, 256>>>(atom_emb, fc0_w2, N, NA);
    phase1_kernel<<<GP, 256>>>(an, coords, ei, fc0_w1, fc1_w1, E);
    phase2_kernel<<<GP, 256>>>(ei, fc1_w2, w_readout, out, E);
}